// round 14
// baseline (speedup 1.0000x reference)
#include <cuda_runtime.h>
#include <cuda_bf16.h>
#include <cstdint>

#define BATCH 16384
#define TDIM 1024
#define IDIM 2048
#define NUM_CTAS 148

#if defined(__CUDA_ARCH_FEAT_SM103_ALL) || defined(__CUDA_ARCH_FEAT_SM100_ALL) || defined(__CUDA_ARCH_SPECIFIC__)
#define HAS_TCGEN05 1
#else
#define HAS_TCGEN05 0
#endif

// ======================= device scratch (static, no allocs) =======================
// Packed operand planes, SW64-swizzled 8KB units [kc32][rowblock128].
__device__ __align__(128) __nv_bfloat16 g_text_hi[BATCH * TDIM];
__device__ __align__(128) __nv_bfloat16 g_text_lo[BATCH * TDIM];
__device__ __align__(128) __nv_bfloat16 g_img_hi[BATCH * IDIM];
__device__ __align__(128) __nv_bfloat16 g_img_lo[BATCH * IDIM];
__device__ __align__(128) __nv_bfloat16 g_wq_hi[TDIM * TDIM];
__device__ __align__(128) __nv_bfloat16 g_wq_lo[TDIM * TDIM];
__device__ __align__(128) __nv_bfloat16 g_wk_hi[TDIM * IDIM];
__device__ __align__(128) __nv_bfloat16 g_wk_lo[TDIM * IDIM];
__device__ __align__(128) __nv_bfloat16 g_wv_hi[TDIM * IDIM];
__device__ __align__(128) __nv_bfloat16 g_wv_lo[TDIM * IDIM];
__device__ float g_Q[BATCH * TDIM];
__device__ float g_K[BATCH * TDIM];
__device__ float g_V[BATCH * TDIM];

// device-wide sync state (all 148 CTAs co-resident). g_bar_* is sense-reversing;
// pack-progress counters are reset at the kernel tail so every graph replay
// starts from zero.
__device__ int g_bar_ctr;
__device__ int g_bar_flag;
__device__ int g_text_ctr;
__device__ int g_text_flag;
__device__ int g_w_ctr;          // weights packed: counts CTAs (== NUM_CTAS when ready)
__device__ int g_slab_ctr[64];   // img K-slab kc packed: counts CTAs

// ======================= PTX helpers =======================
__device__ __forceinline__ uint32_t smem_u32(const void* p) {
    uint32_t a;
    asm("{ .reg .u64 t; cvta.to.shared.u64 t, %1; cvt.u32.u64 %0, t; }" : "=r"(a) : "l"(p));
    return a;
}

__device__ __forceinline__ uint32_t elect_one_pred() {
    uint32_t pred;
    asm volatile(
        "{\n\t.reg .pred p;\n\telect.sync _|p, 0xFFFFFFFF;\n\tselp.b32 %0, 1, 0, p;\n\t}"
        : "=r"(pred));
    return pred;
}

#define TCGEN05_ALLOC(smem_result_addr, nCols) \
    asm volatile("tcgen05.alloc.cta_group::1.sync.aligned.shared::cta.b32 [%0], %1;" \
                 :: "r"((uint32_t)(smem_result_addr)), "r"((uint32_t)(nCols)) : "memory")
#define TCGEN05_DEALLOC(tmem_addr, nCols) \
    asm volatile("tcgen05.dealloc.cta_group::1.sync.aligned.b32 %0, %1;" \
                 :: "r"(tmem_addr), "r"((uint32_t)(nCols)))
#define TCGEN05_RELINQUISH() \
    asm volatile("tcgen05.relinquish_alloc_permit.cta_group::1.sync.aligned;")
#define TCGEN05_COMMIT(mbar) \
    asm volatile("tcgen05.commit.cta_group::1.mbarrier::arrive::one.shared::cluster.b64 [%0];" \
                 :: "r"((uint32_t)(mbar)) : "memory")
#define TCGEN05_FENCE_BEFORE() asm volatile("tcgen05.fence::before_thread_sync;" ::: "memory")
#define TCGEN05_FENCE_AFTER()  asm volatile("tcgen05.fence::after_thread_sync;" ::: "memory")
#define TCGEN05_WAIT_LD()      asm volatile("tcgen05.wait::ld.sync.aligned;" ::: "memory")

#define MBARRIER_INIT(mbar, count) \
    asm volatile("mbarrier.init.shared.b64 [%0], %1;" \
                 :: "r"((uint32_t)(mbar)), "r"((uint32_t)(count)) : "memory")
#define MBARRIER_INVAL(mbar) \
    asm volatile("mbarrier.inval.shared.b64 [%0];" :: "r"((uint32_t)(mbar)) : "memory")
#define MBARRIER_EXPECT_TX(mbar, tx_bytes) \
    asm volatile("mbarrier.arrive.expect_tx.shared.b64 _, [%0], %1;" \
                 :: "r"((uint32_t)(mbar)), "r"((uint32_t)(tx_bytes)) : "memory")
#define MBARRIER_ARRIVE(mbar) \
    asm volatile("mbarrier.arrive.shared.b64 _, [%0];" :: "r"((uint32_t)(mbar)) : "memory")

#define MBARRIER_WAIT_PARITY(mbar_smem_addr, phase_parity) do { \
    uint32_t _mbar = (uint32_t)(mbar_smem_addr); \
    uint32_t _parity = (uint32_t)(phase_parity); \
    uint32_t _done; \
    asm volatile( \
        "{\n\t.reg .pred p;\n\t" \
        "mbarrier.try_wait.parity.acquire.cta.shared::cta.b64 p, [%1], %2;\n\t" \
        "selp.b32 %0, 1, 0, p;\n\t}" \
        : "=r"(_done) : "r"(_mbar), "r"(_parity) : "memory"); \
    if (!_done) { \
        asm volatile( \
            "{\n\t.reg .pred P1;\n\t" \
            "WAIT_LOOP_%=:\n\t" \
            "mbarrier.try_wait.parity.acquire.cta.shared::cta.b64 P1, [%0], %1, 0x989680;\n\t" \
            "@P1 bra.uni WAIT_DONE_%=;\n\t" \
            "bra.uni WAIT_LOOP_%=;\n\t" \
            "WAIT_DONE_%=:\n\t}" \
            :: "r"(_mbar), "r"(_parity) : "memory"); \
    } \
} while (0)

#define CP_ASYNC_BULK(dst_smem, src_gmem, nbytes, mbar) \
    asm volatile("cp.async.bulk.shared::cluster.global.mbarrier::complete_tx::bytes " \
                 "[%0], [%1], %2, [%3];" \
                 :: "r"((uint32_t)(dst_smem)), "l"(src_gmem), "r"((uint32_t)(nbytes)), \
                    "r"((uint32_t)(mbar)) : "memory")

#define TCGEN05_LD_32X32B_X32(r, tmem_addr) \
    asm volatile( \
        "tcgen05.ld.sync.aligned.32x32b.x32.b32 " \
        "{%0, %1, %2, %3, %4, %5, %6, %7, " \
        " %8, %9, %10, %11, %12, %13, %14, %15, " \
        " %16, %17, %18, %19, %20, %21, %22, %23, " \
        " %24, %25, %26, %27, %28, %29, %30, %31}, [%32];" \
        : "=r"((r)[0]),  "=r"((r)[1]),  "=r"((r)[2]),  "=r"((r)[3]), \
          "=r"((r)[4]),  "=r"((r)[5]),  "=r"((r)[6]),  "=r"((r)[7]), \
          "=r"((r)[8]),  "=r"((r)[9]),  "=r"((r)[10]), "=r"((r)[11]), \
          "=r"((r)[12]), "=r"((r)[13]), "=r"((r)[14]), "=r"((r)[15]), \
          "=r"((r)[16]), "=r"((r)[17]), "=r"((r)[18]), "=r"((r)[19]), \
          "=r"((r)[20]), "=r"((r)[21]), "=r"((r)[22]), "=r"((r)[23]), \
          "=r"((r)[24]), "=r"((r)[25]), "=r"((r)[26]), "=r"((r)[27]), \
          "=r"((r)[28]), "=r"((r)[29]), "=r"((r)[30]), "=r"((r)[31]) \
        : "r"(tmem_addr))

// SW64 = Swizzle<2,4,3>: bits[4:6) ^= bits[7:9)
#define SMEM_SWIZZLE_64B(byte_offset) ((byte_offset) ^ (((byte_offset) >> 3) & 0x30))

// SW64 K-major descriptor: layout=4, version=1, SBO=32, LBO=1
static constexpr uint64_t SMEM_DESC_BASE_SW64 =
    (uint64_t(4) << 61) | (uint64_t(1) << 46) | (uint64_t(32) << 32) | (uint64_t(1) << 16);
#define MAKE_SMEM_DESC64(base_addr) \
    (SMEM_DESC_BASE_SW64 | ((uint64_t)((base_addr) >> 4) & 0x3FFF))

#if HAS_TCGEN05
__device__ __forceinline__ void mma_f16_ss(uint32_t d_tmem, uint64_t a_desc, uint64_t b_desc,
                                           uint32_t idesc, uint32_t en) {
    asm volatile(
        "{\n\t.reg .pred p;\n\tsetp.ne.u32 p, %5, 0;\n\t"
        "tcgen05.mma.cta_group::1.kind::f16 [%0], %1, %2, %3, {%4, %4, %4, %4}, p;\n\t}"
        :: "r"(d_tmem), "l"(a_desc), "l"(b_desc), "r"(idesc), "r"(0u), "r"(en)
        : "memory");
}
#endif

// ======================= static balanced tile schedule =======================
// Q gemm 256 tiles (nk=32), K 256 (nk=64), V 256 (nk=64). KV list = K then V.
// Q tiles are always LAST in a CTA's list (text-pack gate relies on this).
__device__ __forceinline__ int cta_tile_count(int bid) {
    return bid < 16 ? 5 : (bid < 68 ? 4 : 6);
}
__device__ __forceinline__ void get_tile(int bid, int i, int& kind, int& idx) {
    if (bid < 68) {
        if (i < 4) { int kv = bid * 4 + i; kind = kv < 256 ? 1 : 2; idx = kv & 255; }
        else       { kind = 0; idx = 240 + bid; }
    } else {
        if (i < 3) { int kv = 272 + (bid - 68) * 3 + i; kind = kv < 256 ? 1 : 2; idx = kv & 255; }
        else       { kind = 0; idx = (bid - 68) * 3 + (i - 3); }
    }
}

// ======================= pack fp32 -> SW64 bf16 hi/lo planes =======================
__device__ __forceinline__ void pack_unit(const float* __restrict__ src,
                                          char* __restrict__ hi, char* __restrict__ lo,
                                          int idx, int kg_shift, int nm128) {
    int row = idx >> kg_shift;
    int g = idx & ((1 << kg_shift) - 1);
    int kc = g >> 2, c8 = g & 3;
    int m = row >> 7, r = row & 127;
    const float4* s = (const float4*)(src + ((size_t)row << (kg_shift + 3)) + kc * 32 + c8 * 8);
    float4 x0 = s[0], x1 = s[1];
    float f[8] = {x0.x, x0.y, x0.z, x0.w, x1.x, x1.y, x1.z, x1.w};
    __nv_bfloat16 h[8], l[8];
    #pragma unroll
    for (int i = 0; i < 8; ++i) {
        h[i] = __float2bfloat16_rn(f[i]);
        l[i] = __float2bfloat16_rn(f[i] - __bfloat162float(h[i]));
    }
    uint4 hv, lv;
    __nv_bfloat162* hp = (__nv_bfloat162*)&hv;
    __nv_bfloat162* lp = (__nv_bfloat162*)&lv;
    #pragma unroll
    for (int j = 0; j < 4; ++j) {
        hp[j] = __halves2bfloat162(h[2 * j], h[2 * j + 1]);
        lp[j] = __halves2bfloat162(l[2 * j], l[2 * j + 1]);
    }
    size_t ub = (size_t)(kc * nm128 + m) * 8192;
    uint32_t off = SMEM_SWIZZLE_64B((uint32_t)(r * 64 + c8 * 16));
    *(uint4*)(hi + ub + off) = hv;
    *(uint4*)(lo + ub + off) = lv;
}

// fallback-path unpack (generic pass only)
__device__ __forceinline__ float unpack_elem(const __nv_bfloat16* hi, const __nv_bfloat16* lo,
                                             int row, int k, int nm128) {
    int kc = k >> 5, c = k & 31, m = row >> 7, r = row & 127;
    size_t ub = (size_t)(kc * nm128 + m) * 8192;
    uint32_t off = SMEM_SWIZZLE_64B((uint32_t)(r * 64 + c * 2));
    return __bfloat162float(*(const __nv_bfloat16*)((const char*)hi + ub + off)) +
           __bfloat162float(*(const __nv_bfloat16*)((const char*)lo + ub + off));
}

// device-wide sense-reversing barrier (all CTAs resident; every thread fences first)
__device__ __forceinline__ void grid_barrier(int tid) {
    __threadfence();
    __syncthreads();
    if (tid == 0) {
        int s = *(volatile int*)&g_bar_flag;
        if (atomicAdd(&g_bar_ctr, 1) == NUM_CTAS - 1) {
            *(volatile int*)&g_bar_ctr = 0;
            __threadfence();
            *(volatile int*)&g_bar_flag = s ^ 1;
        } else {
            while (*(volatile int*)&g_bar_flag == s) __nanosleep(64);
        }
    }
    __syncthreads();
}

#define IMG_UNITS  (BATCH * IDIM / 8)
#define TEXT_UNITS (BATCH * TDIM / 8)
#define WQ_UNITS   (TDIM * TDIM / 8)
#define WKV_UNITS  (TDIM * IDIM / 8)
#define SLAB_UNITS (BATCH * 4)        // img units per K-slab (4 c8-groups per row)

// ======================= persistent fused pack + tcgen05 GEMM =======================
// No serialized phase A: warps 2..9 pack weights, then img K-slab-by-slab (JIT),
// then text, then run the epilogue loop. The producer gates on g_w_ctr once and
// on g_slab_ctr[kc] via a monotonic watermark; Q tiles gate on the text flag.
#define OFF_FULL(s)  (16 + (s) * 8)
#define OFF_EMPTY(s) (48 + (s) * 8)
#define OFF_DONE     80
#define OFF_EPI      88
#define ST_BYTES     65536
#define GEMM_SMEM    (2048 + 3 * ST_BYTES)
#define GEMM_IDESC   0x8400490u  // F32 accum, bf16 x bf16, M=128, N=256

__global__ __launch_bounds__(320) void gemm_persist(
    const float* __restrict__ text, const float* __restrict__ image,
    const float* __restrict__ Wq, const float* __restrict__ Wk, const float* __restrict__ Wv,
    float* __restrict__ Qo, float* __restrict__ Ko, float* __restrict__ Vo) {
    const int bid = blockIdx.x;
    const int tid = threadIdx.x;
    const int wid = tid >> 5;
    const int lane = tid & 31;
    const int nt = cta_tile_count(bid);

    const int tsense = *(volatile int*)&g_text_flag;  // before any toggle this launch

    const char* Ahv[3] = {(const char*)g_text_hi, (const char*)g_img_hi, (const char*)g_img_hi};
    const char* Alv[3] = {(const char*)g_text_lo, (const char*)g_img_lo, (const char*)g_img_lo};
    const char* Bhv[3] = {(const char*)g_wq_hi, (const char*)g_wk_hi, (const char*)g_wv_hi};
    const char* Blv[3] = {(const char*)g_wq_lo, (const char*)g_wk_lo, (const char*)g_wv_lo};
    float* Cv[3] = {Qo, Ko, Vo};
    const int nkv[3] = {32, 64, 64};

#if HAS_TCGEN05
    extern __shared__ char smem[];
    uint32_t sb = smem_u32(smem);

    if (wid == 0) TCGEN05_ALLOC(sb, 512);
    __syncthreads();
    uint32_t tmem_base;
    asm volatile("ld.shared.b32 %0, [%1];" : "=r"(tmem_base) : "r"(sb));
    if (wid == 0) TCGEN05_RELINQUISH();
    if (tid == 0) {
        #pragma unroll
        for (int s = 0; s < 3; ++s) {
            MBARRIER_INIT(sb + OFF_FULL(s), 1);
            MBARRIER_INIT(sb + OFF_EMPTY(s), 1);
        }
        MBARRIER_INIT(sb + OFF_DONE, 1);
        MBARRIER_INIT(sb + OFF_EPI, 8);
    }
    __syncthreads();  // mbarriers live (intra-CTA only)

    if (wid == 0) {
        if (elect_one_pred()) {
            // -------- producer --------
            // weights must be packed before the first B-tile load
            while (*(volatile int*)&g_w_ctr < NUM_CTAS) __nanosleep(128);
            int pc = 0, wm = -1;
            bool qgate = false;
            for (int t = 0; t < nt; ++t) {
                int kind, idx;
                get_tile(bid, t, kind, idx);
                if (kind == 0 && !qgate) {  // text pack must be globally done
                    while (*(volatile int*)&g_text_flag == tsense) __nanosleep(128);
                    qgate = true;
                }
                const char* Ah = Ahv[kind];
                const char* Al = Alv[kind];
                const char* Bh = Bhv[kind];
                const char* Bl = Blv[kind];
                int nk = nkv[kind];
                int bx = idx & 3, by = idx >> 2;
                for (int kc = 0; kc < nk; ++kc, ++pc) {
                    if (kind != 0 && kc > wm) {  // img K-slab kc must be packed
                        while (*(volatile int*)&g_slab_ctr[kc] < NUM_CTAS) __nanosleep(128);
                        wm = kc;
                    }
                    int s = pc % 3, ph = (pc / 3) & 1;
                    MBARRIER_WAIT_PARITY(sb + OFF_EMPTY(s), ph ^ 1);
                    MBARRIER_EXPECT_TX(sb + OFF_FULL(s), ST_BYTES);
                    uint32_t st = sb + 2048 + s * ST_BYTES;
                    size_t au = (size_t)(kc * 128 + 2 * by) * 8192;
                    size_t bu = (size_t)(kc * 8 + 2 * bx) * 8192;
                    CP_ASYNC_BULK(st,         Ah + au, 16384, sb + OFF_FULL(s));
                    CP_ASYNC_BULK(st + 16384, Al + au, 16384, sb + OFF_FULL(s));
                    CP_ASYNC_BULK(st + 32768, Bh + bu, 16384, sb + OFF_FULL(s));
                    CP_ASYNC_BULK(st + 49152, Bl + bu, 16384, sb + OFF_FULL(s));
                }
            }
        }
    } else if (wid == 1) {
        if (elect_one_pred()) {
            // -------- MMA consumer --------
            int cc = 0;
            for (int t = 0; t < nt; ++t) {
                int kind, idx;
                get_tile(bid, t, kind, idx);
                int nk = nkv[kind];
                if (t > 0) MBARRIER_WAIT_PARITY(sb + OFF_EPI, (t - 1) & 1);
                for (int kc = 0; kc < nk; ++kc, ++cc) {
                    int s = cc % 3, ph = (cc / 3) & 1;
                    MBARRIER_WAIT_PARITY(sb + OFF_FULL(s), ph);
                    uint32_t st = sb + 2048 + s * ST_BYTES;
                    uint64_t dAhi = MAKE_SMEM_DESC64(st);
                    uint64_t dAlo = MAKE_SMEM_DESC64(st + 16384);
                    uint64_t dBhi = MAKE_SMEM_DESC64(st + 32768);
                    uint64_t dBlo = MAKE_SMEM_DESC64(st + 49152);
                    #pragma unroll
                    for (int sub = 0; sub < 2; ++sub) {
                        uint32_t d = tmem_base + sub * 256;
                        uint64_t ao = (uint64_t)sub * 512;
                        #pragma unroll
                        for (int ks = 0; ks < 2; ++ks)
                            mma_f16_ss(d, dAhi + ao + ks * 2, dBhi + ks * 2, GEMM_IDESC,
                                       (kc == 0 && ks == 0) ? 0u : 1u);
                        #pragma unroll
                        for (int ks = 0; ks < 2; ++ks)
                            mma_f16_ss(d, dAhi + ao + ks * 2, dBlo + ks * 2, GEMM_IDESC, 1u);
                        #pragma unroll
                        for (int ks = 0; ks < 2; ++ks)
                            mma_f16_ss(d, dAlo + ao + ks * 2, dBhi + ks * 2, GEMM_IDESC, 1u);
                    }
                    if (kc == nk - 1) TCGEN05_COMMIT(sb + OFF_DONE);
                    TCGEN05_COMMIT(sb + OFF_EMPTY(s));
                }
            }
        }
    } else {
        // -------- warps 2..9: pack weights -> img slabs (JIT) -> text -> epilogue ----
        {
            const int pt = bid * 256 + (tid - 64);
            const int pstep = NUM_CTAS * 256;
            // 1. weights (needed by every tile's B operand)
            for (int u = pt; u < WQ_UNITS; u += pstep)
                pack_unit(Wq, (char*)g_wq_hi, (char*)g_wq_lo, u, 7, 8);
            for (int u = pt; u < WKV_UNITS; u += pstep)
                pack_unit(Wk, (char*)g_wk_hi, (char*)g_wk_lo, u, 8, 8);
            for (int u = pt; u < WKV_UNITS; u += pstep)
                pack_unit(Wv, (char*)g_wv_hi, (char*)g_wv_lo, u, 8, 8);
            __threadfence();
            asm volatile("bar.sync 1, 256;" ::: "memory");
            if (tid == 64) atomicAdd(&g_w_ctr, 1);
            // 2. img, one K-slab at a time in kc order
            for (int kc = 0; kc < 64; ++kc) {
                for (int v = pt; v < SLAB_UNITS; v += pstep) {
                    int unit = ((v >> 2) << 8) + kc * 4 + (v & 3);
                    pack_unit(image, (char*)g_img_hi, (char*)g_img_lo, unit, 8, 128);
                }
                __threadfence();
                asm volatile("bar.sync 1, 256;" ::: "memory");
                if (tid == 64) atomicAdd(&g_slab_ctr[kc], 1);
            }
            // 3. text (needed only by Q tiles, which are last)
            for (int u = pt; u < TEXT_UNITS; u += pstep)
                pack_unit(text, (char*)g_text_hi, (char*)g_text_lo, u, 7, 128);
            __threadfence();
            asm volatile("bar.sync 1, 256;" ::: "memory");
            if (tid == 64) {
                if (atomicAdd(&g_text_ctr, 1) == NUM_CTAS - 1) {
                    *(volatile int*)&g_text_ctr = 0;
                    __threadfence();
                    *(volatile int*)&g_text_flag = tsense ^ 1;
                }
            }
        }
        int w4 = wid & 3;
        int sub = (wid < 6) ? 0 : 1;
        for (int t = 0; t < nt; ++t) {
            int kind, idx;
            get_tile(bid, t, kind, idx);
            float* C = Cv[kind];
            int bx = idx & 3, by = idx >> 2;
            MBARRIER_WAIT_PARITY(sb + OFF_DONE, t & 1);
            TCGEN05_FENCE_AFTER();
            int row = by * 256 + sub * 128 + w4 * 32 + lane;
            float* Crow = C + (size_t)row * TDIM + bx * 256;
            uint32_t cb = tmem_base + sub * 256;
            #pragma unroll
            for (int g2 = 0; g2 < 8; ++g2) {
                uint32_t r[32];
                TCGEN05_LD_32X32B_X32(r, cb + g2 * 32);
                TCGEN05_WAIT_LD();
                #pragma unroll
                for (int c4 = 0; c4 < 8; ++c4) {
                    float4 v;
                    v.x = __uint_as_float(r[c4 * 4 + 0]);
                    v.y = __uint_as_float(r[c4 * 4 + 1]);
                    v.z = __uint_as_float(r[c4 * 4 + 2]);
                    v.w = __uint_as_float(r[c4 * 4 + 3]);
                    *(float4*)(Crow + g2 * 32 + c4 * 4) = v;
                }
            }
            TCGEN05_FENCE_BEFORE();
            if (elect_one_pred()) MBARRIER_ARRIVE(sb + OFF_EPI);
        }
    }

    __syncthreads();
    if (tid == 0) {
        #pragma unroll
        for (int s = 0; s < 3; ++s) {
            MBARRIER_INVAL(sb + OFF_FULL(s));
            MBARRIER_INVAL(sb + OFF_EMPTY(s));
        }
        MBARRIER_INVAL(sb + OFF_DONE);
        MBARRIER_INVAL(sb + OFF_EPI);
    }
    __syncthreads();
    if (wid == 0) TCGEN05_DEALLOC(tmem_base, 512);

    // -------- tail: reset pack counters so every graph replay starts clean --------
    grid_barrier(tid);
    if (bid == 0 && tid == 0) {
        g_w_ctr = 0;
        #pragma unroll
        for (int i = 0; i < 64; ++i) g_slab_ctr[i] = 0;
    }
    grid_barrier(tid);
#else
    // ---------- SIMT fallback (generic pass; correct, never expected to run) ----------
    {
        const int nthr = NUM_CTAS * 320;
        int gt = bid * 320 + tid;
        for (int u = gt; u < IMG_UNITS; u += nthr)
            pack_unit(image, (char*)g_img_hi, (char*)g_img_lo, u, 8, 128);
        for (int u = gt; u < TEXT_UNITS; u += nthr)
            pack_unit(text, (char*)g_text_hi, (char*)g_text_lo, u, 7, 128);
        for (int u = gt; u < WQ_UNITS; u += nthr)
            pack_unit(Wq, (char*)g_wq_hi, (char*)g_wq_lo, u, 7, 8);
        for (int u = gt; u < WKV_UNITS; u += nthr)
            pack_unit(Wk, (char*)g_wk_hi, (char*)g_wk_lo, u, 8, 8);
        for (int u = gt; u < WKV_UNITS; u += nthr)
            pack_unit(Wv, (char*)g_wv_hi, (char*)g_wv_lo, u, 8, 8);
    }
    grid_barrier(tid);

    extern __shared__ char smem[];
    float* sA = (float*)smem;                  // [128][33]
    float* sB = (float*)(smem + 128 * 33 * 4); // [128][33]
    const int tx = tid & 15, ty = (tid & 255) >> 4;

    for (int t = 0; t < nt; ++t) {
        int kind, idx;
        get_tile(bid, t, kind, idx);
        const __nv_bfloat16* Ah = (const __nv_bfloat16*)Ahv[kind];
        const __nv_bfloat16* Al = (const __nv_bfloat16*)Alv[kind];
        const __nv_bfloat16* Bh = (const __nv_bfloat16*)Bhv[kind];
        const __nv_bfloat16* Bl = (const __nv_bfloat16*)Blv[kind];
        float* C = Cv[kind];
        int Kg = nkv[kind] * 32;
        int m0 = (idx >> 2) * 256;

        for (int q = 0; q < 4; ++q) {
            int mh = q >> 1, nh = q & 1;
            int n0 = (idx & 3) * 256 + nh * 128;
            float acc[8][8];
            #pragma unroll
            for (int i = 0; i < 8; ++i)
                #pragma unroll
                for (int j = 0; j < 8; ++j) acc[i][j] = 0.f;

            for (int k0 = 0; k0 < Kg; k0 += 32) {
                __syncthreads();
                for (int i = tid; i < 128 * 32; i += 320) {
                    int r = i >> 5, c = i & 31;
                    sA[r * 33 + c] = unpack_elem(Ah, Al, m0 + mh * 128 + r, k0 + c, 128);
                    sB[r * 33 + c] = unpack_elem(Bh, Bl, n0 + r, k0 + c, 8);
                }
                __syncthreads();
                if (tid < 256) {
                    #pragma unroll 8
                    for (int kk = 0; kk < 32; ++kk) {
                        float a[8], bb[8];
                        #pragma unroll
                        for (int i = 0; i < 8; ++i) a[i] = sA[(ty * 8 + i) * 33 + kk];
                        #pragma unroll
                        for (int j = 0; j < 8; ++j) bb[j] = sB[(tx * 8 + j) * 33 + kk];
                        #pragma unroll
                        for (int i = 0; i < 8; ++i)
                            #pragma unroll
                            for (int j = 0; j < 8; ++j)
                                acc[i][j] = fmaf(a[i], bb[j], acc[i][j]);
                    }
                }
            }
            if (tid < 256) {
                #pragma unroll
                for (int i = 0; i < 8; ++i) {
                    int row = m0 + mh * 128 + ty * 8 + i;
                    float* Crow = C + (size_t)row * TDIM + n0 + tx * 8;
                    #pragma unroll
                    for (int j = 0; j < 8; ++j) Crow[j] = acc[i][j];
                }
            }
            __syncthreads();
        }
    }
#endif
}

// ======================= fused bias + attention + residual + LayerNorm ============
// One block per row, 256 threads, all-float4. Key identities:
//   (tid>>5)*128 + (tid&31)*4 == tid*4  -> Q/bias/text/out all use float4 index tid.
//   After shfl reduction every lane holds all 8 scores; attended for thread tid
//   needs only its OWN warp's attn -> attn stays in registers, no sAttn smem.
__global__ __launch_bounds__(256) void attn_ln_kernel(
    const float* __restrict__ Q, const float* __restrict__ K, const float* __restrict__ V,
    const float* __restrict__ bq, const float* __restrict__ bk, const float* __restrict__ bv,
    const float* __restrict__ text, const float* __restrict__ gamma,
    const float* __restrict__ beta, float* __restrict__ out) {
    __shared__ float4 sK4[256], sV4[256];
    __shared__ float red[16];
    const int b = blockIdx.x;
    const int tid = threadIdx.x;
    const int w = tid >> 5, lane = tid & 31;
    const size_t base4 = (size_t)b * 256;

    const float4* Q4 = (const float4*)Q;
    const float4* K4 = (const float4*)K;
    const float4* V4 = (const float4*)V;
    const float4* T4 = (const float4*)text;

    // K,V (+bias) to smem; Q (+bias) stays in registers (own-head slice = index tid)
    {
        float4 kk = K4[base4 + tid];
        float4 kb = __ldg(&((const float4*)bk)[tid]);
        kk.x += kb.x; kk.y += kb.y; kk.z += kb.z; kk.w += kb.w;
        sK4[tid] = kk;
        float4 vv = V4[base4 + tid];
        float4 vb = __ldg(&((const float4*)bv)[tid]);
        vv.x += vb.x; vv.y += vb.y; vv.z += vb.z; vv.w += vb.w;
        sV4[tid] = vv;
    }
    float4 q = Q4[base4 + tid];
    {
        float4 qb = __ldg(&((const float4*)bq)[tid]);
        q.x += qb.x; q.y += qb.y; q.z += qb.z; q.w += qb.w;
    }
    __syncthreads();

    // scores for head w over all g (after reduce, ALL lanes hold each sc[g])
    float sc[8];
    #pragma unroll
    for (int g = 0; g < 8; ++g) {
        float4 kk = sK4[g * 32 + lane];
        float s = q.x * kk.x + q.y * kk.y + q.z * kk.z + q.w * kk.w;
        #pragma unroll
        for (int o = 16; o; o >>= 1) s += __shfl_xor_sync(0xffffffffu, s, o);
        sc[g] = s * 0.08838834764831845f;  // 1/sqrt(128)
    }
    float m = sc[0];
    #pragma unroll
    for (int g = 1; g < 8; ++g) m = fmaxf(m, sc[g]);
    float den = 0.f;
    #pragma unroll
    for (int g = 0; g < 8; ++g) { sc[g] = __expf(sc[g] - m); den += sc[g]; }
    float inv = 1.f / den;
    #pragma unroll
    for (int g = 0; g < 8; ++g) sc[g] *= inv;

    // attended (head w, dims 4*tid..4*tid+3) + residual
    float4 x = T4[base4 + tid];
    float4 a = make_float4(0.f, 0.f, 0.f, 0.f);
    #pragma unroll
    for (int g = 0; g < 8; ++g) {
        float4 vv = sV4[g * 32 + lane];
        a.x = fmaf(sc[g], vv.x, a.x);
        a.y = fmaf(sc[g], vv.y, a.y);
        a.z = fmaf(sc[g], vv.z, a.z);
        a.w = fmaf(sc[g], vv.w, a.w);
    }
    x.x += a.x; x.y += a.y; x.z += a.z; x.w += a.w;

    float sum = x.x + x.y + x.z + x.w;
    float sumsq = x.x * x.x + x.y * x.y + x.z * x.z + x.w * x.w;
    #pragma unroll
    for (int o = 16; o; o >>= 1) {
        sum += __shfl_xor_sync(0xffffffffu, sum, o);
        sumsq += __shfl_xor_sync(0xffffffffu, sumsq, o);
    }
    if (lane == 0) { red[w] = sum; red[8 + w] = sumsq; }
    __syncthreads();
    float ts = 0.f, tq = 0.f;
    #pragma unroll
    for (int i = 0; i < 8; ++i) { ts += red[i]; tq += red[8 + i]; }
    float mu = ts * (1.f / 1024.f);
    float var = tq * (1.f / 1024.f) - mu * mu;
    float rstd = rsqrtf(var + 1e-5f);

    float4 gm = __ldg(&((const float4*)gamma)[tid]);
    float4 bt = __ldg(&((const float4*)beta)[tid]);
    float4 o4;
    o4.x = (x.x - mu) * rstd * gm.x + bt.x;
    o4.y = (x.y - mu) * rstd * gm.y + bt.y;
    o4.z = (x.z - mu) * rstd * gm.z + bt.z;
    o4.w = (x.w - mu) * rstd * gm.w + bt.w;
    ((float4*)out)[base4 + tid] = o4;
}

// ======================= host =======================
extern "C" void kernel_launch(void* const* d_in, const int* in_sizes, int n_in,
                              void* d_out, int out_size) {
    const float* text  = (const float*)d_in[0];
    const float* image = (const float*)d_in[1];
    const float* Wq    = (const float*)d_in[2];
    const float* bq    = (const float*)d_in[3];
    const float* Wk    = (const float*)d_in[4];
    const float* bk    = (const float*)d_in[5];
    const float* Wv    = (const float*)d_in[6];
    const float* bv    = (const float*)d_in[7];
    const float* gamma = (const float*)d_in[8];
    const float* beta  = (const float*)d_in[9];
    float* out = (float*)d_out;

    void *pQ, *pK, *pV;
    cudaGetSymbolAddress(&pQ, g_Q);
    cudaGetSymbolAddress(&pK, g_K);
    cudaGetSymbolAddress(&pV, g_V);

    cudaFuncSetAttribute(gemm_persist, cudaFuncAttributeMaxDynamicSharedMemorySize, GEMM_SMEM);

    gemm_persist<<<NUM_CTAS, 320, GEMM_SMEM>>>(
        text, image, Wq, Wk, Wv, (float*)pQ, (float*)pK, (float*)pV);

    attn_ln_kernel<<<BATCH, 256>>>((const float*)pQ, (const float*)pK, (const float*)pV,
                                   bq, bk, bv, text, gamma, beta, out);
}

// round 16
// speedup vs baseline: 1.0987x; 1.0987x over previous
#include <cuda_runtime.h>
#include <cuda_bf16.h>
#include <cstdint>

#define BATCH 16384
#define TDIM 1024
#define IDIM 2048
#define NUM_CTAS 148

#if defined(__CUDA_ARCH_FEAT_SM103_ALL) || defined(__CUDA_ARCH_FEAT_SM100_ALL) || defined(__CUDA_ARCH_SPECIFIC__)
#define HAS_TCGEN05 1
#else
#define HAS_TCGEN05 0
#endif

// ======================= device scratch (static, no allocs) =======================
// Packed operand planes, SW64-swizzled 8KB units [kc32][rowblock128].
__device__ __align__(128) __nv_bfloat16 g_text_hi[BATCH * TDIM];
__device__ __align__(128) __nv_bfloat16 g_text_lo[BATCH * TDIM];
__device__ __align__(128) __nv_bfloat16 g_img_hi[BATCH * IDIM];
__device__ __align__(128) __nv_bfloat16 g_img_lo[BATCH * IDIM];
__device__ __align__(128) __nv_bfloat16 g_wq_hi[TDIM * TDIM];
__device__ __align__(128) __nv_bfloat16 g_wq_lo[TDIM * TDIM];
__device__ __align__(128) __nv_bfloat16 g_wk_hi[TDIM * IDIM];
__device__ __align__(128) __nv_bfloat16 g_wk_lo[TDIM * IDIM];
__device__ __align__(128) __nv_bfloat16 g_wv_hi[TDIM * IDIM];
__device__ __align__(128) __nv_bfloat16 g_wv_lo[TDIM * IDIM];
__device__ float g_Q[BATCH * TDIM];
__device__ float g_K[BATCH * TDIM];
__device__ float g_V[BATCH * TDIM];

// device-wide barrier state (all 148 CTAs co-resident; sense-reversing so every
// graph replay starts from a consistent state).
__device__ int g_bar_ctr;
__device__ int g_bar_flag;
__device__ int g_text_ctr;
__device__ int g_text_flag;

// ======================= PTX helpers =======================
__device__ __forceinline__ uint32_t smem_u32(const void* p) {
    uint32_t a;
    asm("{ .reg .u64 t; cvta.to.shared.u64 t, %1; cvt.u32.u64 %0, t; }" : "=r"(a) : "l"(p));
    return a;
}

__device__ __forceinline__ uint32_t elect_one_pred() {
    uint32_t pred;
    asm volatile(
        "{\n\t.reg .pred p;\n\telect.sync _|p, 0xFFFFFFFF;\n\tselp.b32 %0, 1, 0, p;\n\t}"
        : "=r"(pred));
    return pred;
}

#define TCGEN05_ALLOC(smem_result_addr, nCols) \
    asm volatile("tcgen05.alloc.cta_group::1.sync.aligned.shared::cta.b32 [%0], %1;" \
                 :: "r"((uint32_t)(smem_result_addr)), "r"((uint32_t)(nCols)) : "memory")
#define TCGEN05_DEALLOC(tmem_addr, nCols) \
    asm volatile("tcgen05.dealloc.cta_group::1.sync.aligned.b32 %0, %1;" \
                 :: "r"(tmem_addr), "r"((uint32_t)(nCols)))
#define TCGEN05_RELINQUISH() \
    asm volatile("tcgen05.relinquish_alloc_permit.cta_group::1.sync.aligned;")
#define TCGEN05_COMMIT(mbar) \
    asm volatile("tcgen05.commit.cta_group::1.mbarrier::arrive::one.shared::cluster.b64 [%0];" \
                 :: "r"((uint32_t)(mbar)) : "memory")
#define TCGEN05_FENCE_BEFORE() asm volatile("tcgen05.fence::before_thread_sync;" ::: "memory")
#define TCGEN05_FENCE_AFTER()  asm volatile("tcgen05.fence::after_thread_sync;" ::: "memory")
#define TCGEN05_WAIT_LD()      asm volatile("tcgen05.wait::ld.sync.aligned;" ::: "memory")

#define MBARRIER_INIT(mbar, count) \
    asm volatile("mbarrier.init.shared.b64 [%0], %1;" \
                 :: "r"((uint32_t)(mbar)), "r"((uint32_t)(count)) : "memory")
#define MBARRIER_INVAL(mbar) \
    asm volatile("mbarrier.inval.shared.b64 [%0];" :: "r"((uint32_t)(mbar)) : "memory")
#define MBARRIER_EXPECT_TX(mbar, tx_bytes) \
    asm volatile("mbarrier.arrive.expect_tx.shared.b64 _, [%0], %1;" \
                 :: "r"((uint32_t)(mbar)), "r"((uint32_t)(tx_bytes)) : "memory")
#define MBARRIER_ARRIVE(mbar) \
    asm volatile("mbarrier.arrive.shared.b64 _, [%0];" :: "r"((uint32_t)(mbar)) : "memory")

#define MBARRIER_WAIT_PARITY(mbar_smem_addr, phase_parity) do { \
    uint32_t _mbar = (uint32_t)(mbar_smem_addr); \
    uint32_t _parity = (uint32_t)(phase_parity); \
    uint32_t _done; \
    asm volatile( \
        "{\n\t.reg .pred p;\n\t" \
        "mbarrier.try_wait.parity.acquire.cta.shared::cta.b64 p, [%1], %2;\n\t" \
        "selp.b32 %0, 1, 0, p;\n\t}" \
        : "=r"(_done) : "r"(_mbar), "r"(_parity) : "memory"); \
    if (!_done) { \
        asm volatile( \
            "{\n\t.reg .pred P1;\n\t" \
            "WAIT_LOOP_%=:\n\t" \
            "mbarrier.try_wait.parity.acquire.cta.shared::cta.b64 P1, [%0], %1, 0x989680;\n\t" \
            "@P1 bra.uni WAIT_DONE_%=;\n\t" \
            "bra.uni WAIT_LOOP_%=;\n\t" \
            "WAIT_DONE_%=:\n\t}" \
            :: "r"(_mbar), "r"(_parity) : "memory"); \
    } \
} while (0)

#define CP_ASYNC_BULK(dst_smem, src_gmem, nbytes, mbar) \
    asm volatile("cp.async.bulk.shared::cluster.global.mbarrier::complete_tx::bytes " \
                 "[%0], [%1], %2, [%3];" \
                 :: "r"((uint32_t)(dst_smem)), "l"(src_gmem), "r"((uint32_t)(nbytes)), \
                    "r"((uint32_t)(mbar)) : "memory")

#define TCGEN05_LD_32X32B_X32(r, tmem_addr) \
    asm volatile( \
        "tcgen05.ld.sync.aligned.32x32b.x32.b32 " \
        "{%0, %1, %2, %3, %4, %5, %6, %7, " \
        " %8, %9, %10, %11, %12, %13, %14, %15, " \
        " %16, %17, %18, %19, %20, %21, %22, %23, " \
        " %24, %25, %26, %27, %28, %29, %30, %31}, [%32];" \
        : "=r"((r)[0]),  "=r"((r)[1]),  "=r"((r)[2]),  "=r"((r)[3]), \
          "=r"((r)[4]),  "=r"((r)[5]),  "=r"((r)[6]),  "=r"((r)[7]), \
          "=r"((r)[8]),  "=r"((r)[9]),  "=r"((r)[10]), "=r"((r)[11]), \
          "=r"((r)[12]), "=r"((r)[13]), "=r"((r)[14]), "=r"((r)[15]), \
          "=r"((r)[16]), "=r"((r)[17]), "=r"((r)[18]), "=r"((r)[19]), \
          "=r"((r)[20]), "=r"((r)[21]), "=r"((r)[22]), "=r"((r)[23]), \
          "=r"((r)[24]), "=r"((r)[25]), "=r"((r)[26]), "=r"((r)[27]), \
          "=r"((r)[28]), "=r"((r)[29]), "=r"((r)[30]), "=r"((r)[31]) \
        : "r"(tmem_addr))

// SW64 = Swizzle<2,4,3>: bits[4:6) ^= bits[7:9)
#define SMEM_SWIZZLE_64B(byte_offset) ((byte_offset) ^ (((byte_offset) >> 3) & 0x30))

// SW64 K-major descriptor: layout=4, version=1, SBO=32, LBO=1
static constexpr uint64_t SMEM_DESC_BASE_SW64 =
    (uint64_t(4) << 61) | (uint64_t(1) << 46) | (uint64_t(32) << 32) | (uint64_t(1) << 16);
#define MAKE_SMEM_DESC64(base_addr) \
    (SMEM_DESC_BASE_SW64 | ((uint64_t)((base_addr) >> 4) & 0x3FFF))

#if HAS_TCGEN05
__device__ __forceinline__ void mma_f16_ss(uint32_t d_tmem, uint64_t a_desc, uint64_t b_desc,
                                           uint32_t idesc, uint32_t en) {
    asm volatile(
        "{\n\t.reg .pred p;\n\tsetp.ne.u32 p, %5, 0;\n\t"
        "tcgen05.mma.cta_group::1.kind::f16 [%0], %1, %2, %3, {%4, %4, %4, %4}, p;\n\t}"
        :: "r"(d_tmem), "l"(a_desc), "l"(b_desc), "r"(idesc), "r"(0u), "r"(en)
        : "memory");
}
#endif

// ======================= static balanced tile schedule =======================
// Q gemm 256 tiles (nk=32), K 256 (nk=64), V 256 (nk=64). KV list = K then V.
// Q tiles are always LAST in a CTA's list (text-pack gate relies on this).
__device__ __forceinline__ int cta_tile_count(int bid) {
    return bid < 16 ? 5 : (bid < 68 ? 4 : 6);
}
__device__ __forceinline__ void get_tile(int bid, int i, int& kind, int& idx) {
    if (bid < 68) {
        if (i < 4) { int kv = bid * 4 + i; kind = kv < 256 ? 1 : 2; idx = kv & 255; }
        else       { kind = 0; idx = 240 + bid; }
    } else {
        if (i < 3) { int kv = 272 + (bid - 68) * 3 + i; kind = kv < 256 ? 1 : 2; idx = kv & 255; }
        else       { kind = 0; idx = (bid - 68) * 3 + (i - 3); }
    }
}

// ======================= pack fp32 -> SW64 bf16 hi/lo planes =======================
__device__ __forceinline__ void pack_unit(const float* __restrict__ src,
                                          char* __restrict__ hi, char* __restrict__ lo,
                                          int idx, int kg_shift, int nm128) {
    int row = idx >> kg_shift;
    int g = idx & ((1 << kg_shift) - 1);
    int kc = g >> 2, c8 = g & 3;
    int m = row >> 7, r = row & 127;
    const float4* s = (const float4*)(src + ((size_t)row << (kg_shift + 3)) + kc * 32 + c8 * 8);
    float4 x0 = s[0], x1 = s[1];
    float f[8] = {x0.x, x0.y, x0.z, x0.w, x1.x, x1.y, x1.z, x1.w};
    __nv_bfloat16 h[8], l[8];
    #pragma unroll
    for (int i = 0; i < 8; ++i) {
        h[i] = __float2bfloat16_rn(f[i]);
        l[i] = __float2bfloat16_rn(f[i] - __bfloat162float(h[i]));
    }
    uint4 hv, lv;
    __nv_bfloat162* hp = (__nv_bfloat162*)&hv;
    __nv_bfloat162* lp = (__nv_bfloat162*)&lv;
    #pragma unroll
    for (int j = 0; j < 4; ++j) {
        hp[j] = __halves2bfloat162(h[2 * j], h[2 * j + 1]);
        lp[j] = __halves2bfloat162(l[2 * j], l[2 * j + 1]);
    }
    size_t ub = (size_t)(kc * nm128 + m) * 8192;
    uint32_t off = SMEM_SWIZZLE_64B((uint32_t)(r * 64 + c8 * 16));
    *(uint4*)(hi + ub + off) = hv;
    *(uint4*)(lo + ub + off) = lv;
}

// fallback-path unpack (generic pass only)
__device__ __forceinline__ float unpack_elem(const __nv_bfloat16* hi, const __nv_bfloat16* lo,
                                             int row, int k, int nm128) {
    int kc = k >> 5, c = k & 31, m = row >> 7, r = row & 127;
    size_t ub = (size_t)(kc * nm128 + m) * 8192;
    uint32_t off = SMEM_SWIZZLE_64B((uint32_t)(r * 64 + c * 2));
    return __bfloat162float(*(const __nv_bfloat16*)((const char*)hi + ub + off)) +
           __bfloat162float(*(const __nv_bfloat16*)((const char*)lo + ub + off));
}

// device-wide sense-reversing barrier (all CTAs resident; every thread fences first)
__device__ __forceinline__ void grid_barrier(int tid) {
    __threadfence();
    __syncthreads();
    if (tid == 0) {
        int s = *(volatile int*)&g_bar_flag;
        if (atomicAdd(&g_bar_ctr, 1) == NUM_CTAS - 1) {
            *(volatile int*)&g_bar_ctr = 0;
            __threadfence();
            *(volatile int*)&g_bar_flag = s ^ 1;
        } else {
            while (*(volatile int*)&g_bar_flag == s) __nanosleep(64);
        }
    }
    __syncthreads();
}

#define IMG_UNITS  (BATCH * IDIM / 8)
#define TEXT_UNITS (BATCH * TDIM / 8)
#define WQ_UNITS   (TDIM * TDIM / 8)
#define WKV_UNITS  (TDIM * IDIM / 8)

// ======================= persistent fused pack + tcgen05 GEMM =======================
// 512 threads: all 16 warps run Phase A (pack img + weights); then warp0 producer,
// warp1 consumer, warps 2..15 pack text (448 threads), warps 2..9 run the epilogue
// loop and warps 10..15 park at the tail barrier.
#define OFF_FULL(s)  (16 + (s) * 8)
#define OFF_EMPTY(s) (48 + (s) * 8)
#define OFF_DONE     80
#define OFF_EPI      88
#define ST_BYTES     65536
#define GEMM_SMEM    (2048 + 3 * ST_BYTES)
#define GEMM_IDESC   0x8400490u  // F32 accum, bf16 x bf16, M=128, N=256
#define NTHREADS     512

__global__ __launch_bounds__(NTHREADS) void gemm_persist(
    const float* __restrict__ text, const float* __restrict__ image,
    const float* __restrict__ Wq, const float* __restrict__ Wk, const float* __restrict__ Wv,
    float* __restrict__ Qo, float* __restrict__ Ko, float* __restrict__ Vo) {
    const int bid = blockIdx.x;
    const int tid = threadIdx.x;
    const int wid = tid >> 5;
    const int lane = tid & 31;
    const int nt = cta_tile_count(bid);

    const int tsense = *(volatile int*)&g_text_flag;  // before any toggle this launch

    const char* Ahv[3] = {(const char*)g_text_hi, (const char*)g_img_hi, (const char*)g_img_hi};
    const char* Alv[3] = {(const char*)g_text_lo, (const char*)g_img_lo, (const char*)g_img_lo};
    const char* Bhv[3] = {(const char*)g_wq_hi, (const char*)g_wk_hi, (const char*)g_wv_hi};
    const char* Blv[3] = {(const char*)g_wq_lo, (const char*)g_wk_lo, (const char*)g_wv_lo};
    float* Cv[3] = {Qo, Ko, Vo};
    const int nkv[3] = {32, 64, 64};

#if HAS_TCGEN05
    extern __shared__ char smem[];
    uint32_t sb = smem_u32(smem);

    if (wid == 0) TCGEN05_ALLOC(sb, 512);
    __syncthreads();
    uint32_t tmem_base;
    asm volatile("ld.shared.b32 %0, [%1];" : "=r"(tmem_base) : "r"(sb));
    if (wid == 0) TCGEN05_RELINQUISH();
    if (tid == 0) {
        #pragma unroll
        for (int s = 0; s < 3; ++s) {
            MBARRIER_INIT(sb + OFF_FULL(s), 1);
            MBARRIER_INIT(sb + OFF_EMPTY(s), 1);
        }
        MBARRIER_INIT(sb + OFF_DONE, 1);
        MBARRIER_INIT(sb + OFF_EPI, 8);
    }

    // -------- Phase A: pack img + weights with ALL 512 threads x 148 CTAs --------
    {
        const int nthr = NUM_CTAS * NTHREADS;
        int gt = bid * NTHREADS + tid;
        for (int u = gt; u < IMG_UNITS; u += nthr)
            pack_unit(image, (char*)g_img_hi, (char*)g_img_lo, u, 8, 128);
        for (int u = gt; u < WQ_UNITS; u += nthr)
            pack_unit(Wq, (char*)g_wq_hi, (char*)g_wq_lo, u, 7, 8);
        for (int u = gt; u < WKV_UNITS; u += nthr)
            pack_unit(Wk, (char*)g_wk_hi, (char*)g_wk_lo, u, 8, 8);
        for (int u = gt; u < WKV_UNITS; u += nthr)
            pack_unit(Wv, (char*)g_wv_hi, (char*)g_wv_lo, u, 8, 8);
    }
    grid_barrier(tid);  // img+weights visible everywhere; mbarriers live

    if (wid == 0) {
        if (elect_one_pred()) {
            // -------- producer --------
            int pc = 0;
            bool qgate = false;
            for (int t = 0; t < nt; ++t) {
                int kind, idx;
                get_tile(bid, t, kind, idx);
                if (kind == 0 && !qgate) {  // text pack must be globally done
                    while (*(volatile int*)&g_text_flag == tsense) __nanosleep(64);
                    qgate = true;
                }
                const char* Ah = Ahv[kind];
                const char* Al = Alv[kind];
                const char* Bh = Bhv[kind];
                const char* Bl = Blv[kind];
                int nk = nkv[kind];
                int bx = idx & 3, by = idx >> 2;
                for (int kc = 0; kc < nk; ++kc, ++pc) {
                    int s = pc % 3, ph = (pc / 3) & 1;
                    MBARRIER_WAIT_PARITY(sb + OFF_EMPTY(s), ph ^ 1);
                    MBARRIER_EXPECT_TX(sb + OFF_FULL(s), ST_BYTES);
                    uint32_t st = sb + 2048 + s * ST_BYTES;
                    size_t au = (size_t)(kc * 128 + 2 * by) * 8192;
                    size_t bu = (size_t)(kc * 8 + 2 * bx) * 8192;
                    CP_ASYNC_BULK(st,         Ah + au, 16384, sb + OFF_FULL(s));
                    CP_ASYNC_BULK(st + 16384, Al + au, 16384, sb + OFF_FULL(s));
                    CP_ASYNC_BULK(st + 32768, Bh + bu, 16384, sb + OFF_FULL(s));
                    CP_ASYNC_BULK(st + 49152, Bl + bu, 16384, sb + OFF_FULL(s));
                }
            }
        }
    } else if (wid == 1) {
        if (elect_one_pred()) {
            // -------- MMA consumer --------
            int cc = 0;
            for (int t = 0; t < nt; ++t) {
                int kind, idx;
                get_tile(bid, t, kind, idx);
                int nk = nkv[kind];
                if (t > 0) MBARRIER_WAIT_PARITY(sb + OFF_EPI, (t - 1) & 1);
                for (int kc = 0; kc < nk; ++kc, ++cc) {
                    int s = cc % 3, ph = (cc / 3) & 1;
                    MBARRIER_WAIT_PARITY(sb + OFF_FULL(s), ph);
                    uint32_t st = sb + 2048 + s * ST_BYTES;
                    uint64_t dAhi = MAKE_SMEM_DESC64(st);
                    uint64_t dAlo = MAKE_SMEM_DESC64(st + 16384);
                    uint64_t dBhi = MAKE_SMEM_DESC64(st + 32768);
                    uint64_t dBlo = MAKE_SMEM_DESC64(st + 49152);
                    #pragma unroll
                    for (int sub = 0; sub < 2; ++sub) {
                        uint32_t d = tmem_base + sub * 256;
                        uint64_t ao = (uint64_t)sub * 512;
                        #pragma unroll
                        for (int ks = 0; ks < 2; ++ks)
                            mma_f16_ss(d, dAhi + ao + ks * 2, dBhi + ks * 2, GEMM_IDESC,
                                       (kc == 0 && ks == 0) ? 0u : 1u);
                        #pragma unroll
                        for (int ks = 0; ks < 2; ++ks)
                            mma_f16_ss(d, dAhi + ao + ks * 2, dBlo + ks * 2, GEMM_IDESC, 1u);
                        #pragma unroll
                        for (int ks = 0; ks < 2; ++ks)
                            mma_f16_ss(d, dAlo + ao + ks * 2, dBhi + ks * 2, GEMM_IDESC, 1u);
                    }
                    if (kc == nk - 1) TCGEN05_COMMIT(sb + OFF_DONE);
                    TCGEN05_COMMIT(sb + OFF_EMPTY(s));
                }
            }
        }
    } else {
        // -------- warps 2..15: pack text (448 threads); then warps 2..9 epilogue ----
        {
            int gtw = bid * 448 + (tid - 64);
            for (int u = gtw; u < TEXT_UNITS; u += NUM_CTAS * 448)
                pack_unit(text, (char*)g_text_hi, (char*)g_text_lo, u, 7, 128);
            __threadfence();
            asm volatile("bar.sync 1, 448;" ::: "memory");
            if (tid == 64) {
                if (atomicAdd(&g_text_ctr, 1) == NUM_CTAS - 1) {
                    *(volatile int*)&g_text_ctr = 0;
                    __threadfence();
                    *(volatile int*)&g_text_flag = tsense ^ 1;
                }
            }
        }
        if (wid < 10) {
            int w4 = wid & 3;
            int sub = (wid < 6) ? 0 : 1;
            for (int t = 0; t < nt; ++t) {
                int kind, idx;
                get_tile(bid, t, kind, idx);
                float* C = Cv[kind];
                int bx = idx & 3, by = idx >> 2;
                MBARRIER_WAIT_PARITY(sb + OFF_DONE, t & 1);
                TCGEN05_FENCE_AFTER();
                int row = by * 256 + sub * 128 + w4 * 32 + lane;
                float* Crow = C + (size_t)row * TDIM + bx * 256;
                uint32_t cb = tmem_base + sub * 256;
                #pragma unroll
                for (int g2 = 0; g2 < 8; ++g2) {
                    uint32_t r[32];
                    TCGEN05_LD_32X32B_X32(r, cb + g2 * 32);
                    TCGEN05_WAIT_LD();
                    #pragma unroll
                    for (int c4 = 0; c4 < 8; ++c4) {
                        float4 v;
                        v.x = __uint_as_float(r[c4 * 4 + 0]);
                        v.y = __uint_as_float(r[c4 * 4 + 1]);
                        v.z = __uint_as_float(r[c4 * 4 + 2]);
                        v.w = __uint_as_float(r[c4 * 4 + 3]);
                        *(float4*)(Crow + g2 * 32 + c4 * 4) = v;
                    }
                }
                TCGEN05_FENCE_BEFORE();
                if (elect_one_pred()) MBARRIER_ARRIVE(sb + OFF_EPI);
            }
        }
    }

    __syncthreads();
    if (tid == 0) {
        #pragma unroll
        for (int s = 0; s < 3; ++s) {
            MBARRIER_INVAL(sb + OFF_FULL(s));
            MBARRIER_INVAL(sb + OFF_EMPTY(s));
        }
        MBARRIER_INVAL(sb + OFF_DONE);
        MBARRIER_INVAL(sb + OFF_EPI);
    }
    __syncthreads();
    if (wid == 0) TCGEN05_DEALLOC(tmem_base, 512);
#else
    // ---------- SIMT fallback (generic pass; correct, never expected to run) ----------
    {
        const int nthr = NUM_CTAS * NTHREADS;
        int gt = bid * NTHREADS + tid;
        for (int u = gt; u < IMG_UNITS; u += nthr)
            pack_unit(image, (char*)g_img_hi, (char*)g_img_lo, u, 8, 128);
        for (int u = gt; u < TEXT_UNITS; u += nthr)
            pack_unit(text, (char*)g_text_hi, (char*)g_text_lo, u, 7, 128);
        for (int u = gt; u < WQ_UNITS; u += nthr)
            pack_unit(Wq, (char*)g_wq_hi, (char*)g_wq_lo, u, 7, 8);
        for (int u = gt; u < WKV_UNITS; u += nthr)
            pack_unit(Wk, (char*)g_wk_hi, (char*)g_wk_lo, u, 8, 8);
        for (int u = gt; u < WKV_UNITS; u += nthr)
            pack_unit(Wv, (char*)g_wv_hi, (char*)g_wv_lo, u, 8, 8);
    }
    grid_barrier(tid);

    extern __shared__ char smem[];
    float* sA = (float*)smem;                  // [128][33]
    float* sB = (float*)(smem + 128 * 33 * 4); // [128][33]
    const int tx = tid & 15, ty = (tid & 255) >> 4;

    for (int t = 0; t < nt; ++t) {
        int kind, idx;
        get_tile(bid, t, kind, idx);
        const __nv_bfloat16* Ah = (const __nv_bfloat16*)Ahv[kind];
        const __nv_bfloat16* Al = (const __nv_bfloat16*)Alv[kind];
        const __nv_bfloat16* Bh = (const __nv_bfloat16*)Bhv[kind];
        const __nv_bfloat16* Bl = (const __nv_bfloat16*)Blv[kind];
        float* C = Cv[kind];
        int Kg = nkv[kind] * 32;
        int m0 = (idx >> 2) * 256;

        for (int q = 0; q < 4; ++q) {
            int mh = q >> 1, nh = q & 1;
            int n0 = (idx & 3) * 256 + nh * 128;
            float acc[8][8];
            #pragma unroll
            for (int i = 0; i < 8; ++i)
                #pragma unroll
                for (int j = 0; j < 8; ++j) acc[i][j] = 0.f;

            for (int k0 = 0; k0 < Kg; k0 += 32) {
                __syncthreads();
                for (int i = tid; i < 128 * 32; i += NTHREADS) {
                    int r = i >> 5, c = i & 31;
                    sA[r * 33 + c] = unpack_elem(Ah, Al, m0 + mh * 128 + r, k0 + c, 128);
                    sB[r * 33 + c] = unpack_elem(Bh, Bl, n0 + r, k0 + c, 8);
                }
                __syncthreads();
                if (tid < 256) {
                    #pragma unroll 8
                    for (int kk = 0; kk < 32; ++kk) {
                        float a[8], bb[8];
                        #pragma unroll
                        for (int i = 0; i < 8; ++i) a[i] = sA[(ty * 8 + i) * 33 + kk];
                        #pragma unroll
                        for (int j = 0; j < 8; ++j) bb[j] = sB[(tx * 8 + j) * 33 + kk];
                        #pragma unroll
                        for (int i = 0; i < 8; ++i)
                            #pragma unroll
                            for (int j = 0; j < 8; ++j)
                                acc[i][j] = fmaf(a[i], bb[j], acc[i][j]);
                    }
                }
            }
            if (tid < 256) {
                #pragma unroll
                for (int i = 0; i < 8; ++i) {
                    int row = m0 + mh * 128 + ty * 8 + i;
                    float* Crow = C + (size_t)row * TDIM + n0 + tx * 8;
                    #pragma unroll
                    for (int j = 0; j < 8; ++j) Crow[j] = acc[i][j];
                }
            }
            __syncthreads();
        }
    }
#endif
}

// ======================= fused bias + attention + residual + LayerNorm ============
// One block per row, 256 threads, all-float4. Key identities:
//   (tid>>5)*128 + (tid&31)*4 == tid*4  -> Q/bias/text/out all use float4 index tid.
//   After shfl reduction every lane holds all 8 scores; attended for thread tid
//   needs only its OWN warp's attn -> attn stays in registers, no sAttn smem.
__global__ __launch_bounds__(256) void attn_ln_kernel(
    const float* __restrict__ Q, const float* __restrict__ K, const float* __restrict__ V,
    const float* __restrict__ bq, const float* __restrict__ bk, const float* __restrict__ bv,
    const float* __restrict__ text, const float* __restrict__ gamma,
    const float* __restrict__ beta, float* __restrict__ out) {
    __shared__ float4 sK4[256], sV4[256];
    __shared__ float red[16];
    const int b = blockIdx.x;
    const int tid = threadIdx.x;
    const int w = tid >> 5, lane = tid & 31;
    const size_t base4 = (size_t)b * 256;

    const float4* Q4 = (const float4*)Q;
    const float4* K4 = (const float4*)K;
    const float4* V4 = (const float4*)V;
    const float4* T4 = (const float4*)text;

    // K,V (+bias) to smem; Q (+bias) stays in registers (own-head slice = index tid)
    {
        float4 kk = K4[base4 + tid];
        float4 kb = __ldg(&((const float4*)bk)[tid]);
        kk.x += kb.x; kk.y += kb.y; kk.z += kb.z; kk.w += kb.w;
        sK4[tid] = kk;
        float4 vv = V4[base4 + tid];
        float4 vb = __ldg(&((const float4*)bv)[tid]);
        vv.x += vb.x; vv.y += vb.y; vv.z += vb.z; vv.w += vb.w;
        sV4[tid] = vv;
    }
    float4 q = Q4[base4 + tid];
    {
        float4 qb = __ldg(&((const float4*)bq)[tid]);
        q.x += qb.x; q.y += qb.y; q.z += qb.z; q.w += qb.w;
    }
    __syncthreads();

    // scores for head w over all g (after reduce, ALL lanes hold each sc[g])
    float sc[8];
    #pragma unroll
    for (int g = 0; g < 8; ++g) {
        float4 kk = sK4[g * 32 + lane];
        float s = q.x * kk.x + q.y * kk.y + q.z * kk.z + q.w * kk.w;
        #pragma unroll
        for (int o = 16; o; o >>= 1) s += __shfl_xor_sync(0xffffffffu, s, o);
        sc[g] = s * 0.08838834764831845f;  // 1/sqrt(128)
    }
    float m = sc[0];
    #pragma unroll
    for (int g = 1; g < 8; ++g) m = fmaxf(m, sc[g]);
    float den = 0.f;
    #pragma unroll
    for (int g = 0; g < 8; ++g) { sc[g] = __expf(sc[g] - m); den += sc[g]; }
    float inv = 1.f / den;
    #pragma unroll
    for (int g = 0; g < 8; ++g) sc[g] *= inv;

    // attended (head w, dims 4*tid..4*tid+3) + residual
    float4 x = T4[base4 + tid];
    float4 a = make_float4(0.f, 0.f, 0.f, 0.f);
    #pragma unroll
    for (int g = 0; g < 8; ++g) {
        float4 vv = sV4[g * 32 + lane];
        a.x = fmaf(sc[g], vv.x, a.x);
        a.y = fmaf(sc[g], vv.y, a.y);
        a.z = fmaf(sc[g], vv.z, a.z);
        a.w = fmaf(sc[g], vv.w, a.w);
    }
    x.x += a.x; x.y += a.y; x.z += a.z; x.w += a.w;

    float sum = x.x + x.y + x.z + x.w;
    float sumsq = x.x * x.x + x.y * x.y + x.z * x.z + x.w * x.w;
    #pragma unroll
    for (int o = 16; o; o >>= 1) {
        sum += __shfl_xor_sync(0xffffffffu, sum, o);
        sumsq += __shfl_xor_sync(0xffffffffu, sumsq, o);
    }
    if (lane == 0) { red[w] = sum; red[8 + w] = sumsq; }
    __syncthreads();
    float ts = 0.f, tq = 0.f;
    #pragma unroll
    for (int i = 0; i < 8; ++i) { ts += red[i]; tq += red[8 + i]; }
    float mu = ts * (1.f / 1024.f);
    float var = tq * (1.f / 1024.f) - mu * mu;
    float rstd = rsqrtf(var + 1e-5f);

    float4 gm = __ldg(&((const float4*)gamma)[tid]);
    float4 bt = __ldg(&((const float4*)beta)[tid]);
    float4 o4;
    o4.x = (x.x - mu) * rstd * gm.x + bt.x;
    o4.y = (x.y - mu) * rstd * gm.y + bt.y;
    o4.z = (x.z - mu) * rstd * gm.z + bt.z;
    o4.w = (x.w - mu) * rstd * gm.w + bt.w;
    ((float4*)out)[base4 + tid] = o4;
}

// ======================= host =======================
extern "C" void kernel_launch(void* const* d_in, const int* in_sizes, int n_in,
                              void* d_out, int out_size) {
    const float* text  = (const float*)d_in[0];
    const float* image = (const float*)d_in[1];
    const float* Wq    = (const float*)d_in[2];
    const float* bq    = (const float*)d_in[3];
    const float* Wk    = (const float*)d_in[4];
    const float* bk    = (const float*)d_in[5];
    const float* Wv    = (const float*)d_in[6];
    const float* bv    = (const float*)d_in[7];
    const float* gamma = (const float*)d_in[8];
    const float* beta  = (const float*)d_in[9];
    float* out = (float*)d_out;

    void *pQ, *pK, *pV;
    cudaGetSymbolAddress(&pQ, g_Q);
    cudaGetSymbolAddress(&pK, g_K);
    cudaGetSymbolAddress(&pV, g_V);

    cudaFuncSetAttribute(gemm_persist, cudaFuncAttributeMaxDynamicSharedMemorySize, GEMM_SMEM);

    gemm_persist<<<NUM_CTAS, NTHREADS, GEMM_SMEM>>>(
        text, image, Wq, Wk, Wv, (float*)pQ, (float*)pK, (float*)pV);

    attn_ln_kernel<<<BATCH, 256>>>((const float*)pQ, (const float*)pK, (const float*)pV,
                                   bq, bk, bv, text, gamma, beta, out);
}